// round 12
// baseline (speedup 1.0000x reference)
#include <cuda_runtime.h>
#include <math.h>

#define Bv   16384
#define Tv   60
#define Hv   128
#define NXv  4
#define NYv  4
#define NYSv 3

#define PADA 133   // A_s row pad (odd*? -> conflict-free transpose stores, 133%32=5)
#define PADW 132   // ws row pad (multiple of 4 for LDS.128 alignment)
#define PADC 130   // c_s row pad (even for float2)

typedef unsigned long long ull;

// ---------------- scratch ----------------
__device__ float g_r1[(size_t)Tv * Bv * Hv];
__device__ float g_r2[(size_t)Tv * Bv * Hv];
__device__ float g_h1[Bv * Hv];
__device__ float g_c1[Bv * Hv];
__device__ float g_W1p[260 * 512];   // permuted+transposed [K=260][512]
__device__ float g_W2p[256 * 512];   // [K=256][512]
__device__ float g_b1p[512];
__device__ float g_b2p[512];
__device__ float g_wcomb[NYv * Hv];
__device__ float g_bcomb[NYv];

// ---------------- f32x2 helpers ----------------
__device__ __forceinline__ ull pk2(float x, float y) {
    ull r; asm("mov.b64 %0, {%1, %2};" : "=l"(r) : "f"(x), "f"(y)); return r;
}
__device__ __forceinline__ void upk2(ull v, float& x, float& y) {
    asm("mov.b64 {%0, %1}, %2;" : "=f"(x), "=f"(y) : "l"(v));
}
__device__ __forceinline__ void ffma2(ull& d, ull a, ull b) {
    asm("fma.rn.f32x2 %0, %1, %2, %0;" : "+l"(d) : "l"(a), "l"(b));
}

__device__ __forceinline__ float sigf(float x) {
    return __fdividef(1.0f, 1.0f + __expf(-x));
}
__device__ __forceinline__ float tanhf_(float x) {
    return __fdividef(2.0f, 1.0f + __expf(-2.0f * x)) - 1.0f;
}

// ---------------- init: h0/c0 for layer1 ----------------
__global__ void init_kernel(const float* __restrict__ sfc,
                            const float* __restrict__ Ws1, const float* __restrict__ bs1,
                            const float* __restrict__ Ws2, const float* __restrict__ bs2)
{
    int i = blockIdx.x * blockDim.x + threadIdx.x;
    if (i >= Bv * Hv) return;
    int b = i >> 7, j = i & 127;
    float s0 = sfc[b * 3 + 0], s1 = sfc[b * 3 + 1], s2 = sfc[b * 3 + 2];
    float a1 = bs1[j] + s0 * Ws1[j * 3 + 0] + s1 * Ws1[j * 3 + 1] + s2 * Ws1[j * 3 + 2];
    float a2 = bs2[j] + s0 * Ws2[j * 3 + 0] + s1 * Ws2[j * 3 + 1] + s2 * Ws2[j * 3 + 2];
    g_h1[i] = tanhf(a1);
    g_c1[i] = tanhf(a2);
}

// ---------------- prep: permuted weights/biases + folded output projection ----------------
// Column permutation within each 128-wide chunk ci: n = jj*4 + q  (jj: hidden-in-chunk, q: gate)
__global__ void prep_kernel(const float* __restrict__ Wih1, const float* __restrict__ Whh1,
                            const float* __restrict__ bih1, const float* __restrict__ bhh1,
                            const float* __restrict__ Wih2, const float* __restrict__ Whh2,
                            const float* __restrict__ bih2, const float* __restrict__ bhh2,
                            const float* __restrict__ Wlat, const float* __restrict__ blat,
                            const float* __restrict__ Wout, const float* __restrict__ bout)
{
    int idx = blockIdx.x * blockDim.x + threadIdx.x;
    const int N1 = 260 * 512, N2 = 256 * 512;
    if (idx < N1) {
        int k = idx >> 9, m = idx & 511;
        int ci = m >> 7, n = m & 127, q = n & 3, jj = n >> 2;
        int g = q * 128 + ci * 32 + jj;
        g_W1p[idx] = (k < 132) ? Wih1[g * 132 + k] : Whh1[g * 128 + (k - 132)];
        return;
    }
    int i2 = idx - N1;
    if (i2 < N2) {
        int k = i2 >> 9, m = i2 & 511;
        int ci = m >> 7, n = m & 127, q = n & 3, jj = n >> 2;
        int g = q * 128 + ci * 32 + jj;
        g_W2p[i2] = (k < 128) ? Wih2[g * 128 + k] : Whh2[g * 128 + (k - 128)];
        return;
    }
    int i3 = idx - N1 - N2;
    if (i3 < 512) {
        int ci = i3 >> 7, n = i3 & 127, q = n & 3, jj = n >> 2;
        int g = q * 128 + ci * 32 + jj;
        g_b1p[i3] = bih1[g] + bhh1[g];
        g_b2p[i3] = bih2[g] + bhh2[g];
        // folded output projection: Wcomb = Wout @ Wlat
        int y = i3 >> 7, j = i3 & 127;
        float acc = 0.0f;
        for (int k = 0; k < Hv; k++) acc += Wout[y * Hv + k] * Wlat[k * Hv + j];
        g_wcomb[i3] = acc;
        if (i3 < NYv) {
            float bb = bout[i3];
            for (int k = 0; k < Hv; k++) bb += Wout[i3 * Hv + k] * blat[k];
            g_bcomb[i3] = bb;
        }
    }
}

// ---------------- persistent fused 2-layer LSTM ----------------
// Grid: 128 CTAs x 256 threads. CTA owns batch rows [cta*128, cta*128+128).
// Runs layer1 (reverse time) then layer2 (forward), 60 steps each, locally.
// Inner GEMM: M=128 x N=128-chunk x K, f32x2 packed FMA, 8 rows x 4 col-pairs per thread.
__global__ __launch_bounds__(256, 1) void rnn_persist(
    const float* __restrict__ inputs_main,   // [B][T][4]
    const float* __restrict__ mem0,          // [B][T][128]
    const float* __restrict__ h1_0, const float* __restrict__ c1_0,
    const float* __restrict__ hx2,  const float* __restrict__ cx2,
    const float* __restrict__ W1p,  const float* __restrict__ b1p,
    const float* __restrict__ W2p,  const float* __restrict__ b2p,
    float* __restrict__ r1, float* __restrict__ r2)
{
    extern __shared__ float sm[];
    float* A_s    = sm;                           // [260][PADA] K-major activations
    float* c_s    = sm + 260 * PADA;              // [128][PADC]
    float* ws     = c_s + 128 * PADC;             // [32][PADW]  weight panel
    float* bias_s = ws + 32 * PADW;               // [512]

    const int tid = threadIdx.x;
    const int tx = tid & 15;
    const int ty = tid >> 4;
    const int b0 = blockIdx.x * 128;
    const size_t SLAB = (size_t)Bv * Hv;

    for (int layer = 0; layer < 2; ++layer) {
        const int KA   = layer ? 128 : 132;   // non-recurrent K
        const int KTOT = KA + 128;
        const int NPAN = (KTOT + 31) >> 5;
        const float* Wp = layer ? W2p : W1p;
        const float* bp = layer ? b2p : b1p;

        // load bias + initial c for this layer
        __syncthreads();
        for (int i = tid; i < 512; i += 256) bias_s[i] = bp[i];
        {
            const float* c0 = layer ? cx2 : c1_0;
            for (int i = tid; i < 128 * 128; i += 256) {
                int r = i >> 7, k = i & 127;
                c_s[r * PADC + k] = c0[(size_t)(b0 + r) * 128 + k];
            }
        }

        for (int t = 0; t < Tv; ++t) {
            const int ta = layer ? t : (Tv - 1 - t);   // actual time index
            const float* hsrc = (t == 0)
                ? (layer ? hx2 : h1_0)
                : (layer ? r2 + (size_t)(t - 1) * SLAB : r1 + (size_t)(ta + 1) * SLAB);
            float* hdst = layer ? r2 + (size_t)t * SLAB : r1 + (size_t)ta * SLAB;

            __syncthreads();   // protect A_s / ws from previous step's readers

            // ---- stage activations K-major into A_s ----
            if (layer == 0) {
                for (int i = tid; i < 512; i += 256) {           // x: k 0..3
                    int r = i >> 2, f = i & 3;
                    A_s[f * PADA + r] = inputs_main[(size_t)(b0 + r) * (Tv * NXv) + ta * NXv + f];
                }
                for (int i = tid; i < 128 * 128; i += 256) {     // mem0: k 4..131
                    int r = i >> 7, k = i & 127;
                    A_s[(4 + k) * PADA + r] = mem0[(size_t)(b0 + r) * (Tv * Hv) + t * Hv + k];
                }
            } else {
                for (int i = tid; i < 128 * 128; i += 256) {     // r1_t: k 0..127
                    int r = i >> 7, k = i & 127;
                    A_s[k * PADA + r] = r1[(size_t)t * SLAB + (size_t)(b0 + r) * 128 + k];
                }
            }
            for (int i = tid; i < 128 * 128; i += 256) {         // h: k KA..KA+127
                int r = i >> 7, k = i & 127;
                A_s[(KA + k) * PADA + r] = hsrc[(size_t)(b0 + r) * 128 + k];
            }

            // ---- 4 N-chunks of 128 permuted gate-columns ----
            for (int ci = 0; ci < 4; ++ci) {
                ull acc[8][4];
#pragma unroll
                for (int p = 0; p < 4; ++p) {
                    float2 bb = *(const float2*)&bias_s[ci * 128 + 8 * tx + 2 * p];
                    ull bv = pk2(bb.x, bb.y);
#pragma unroll
                    for (int i = 0; i < 8; i++) acc[i][p] = bv;
                }

                for (int p = 0; p < NPAN; ++p) {
                    const int kbase = p * 32;
                    const int pkk = (kbase + 32 <= KTOT) ? 32 : (KTOT - kbase);
                    __syncthreads();
                    const float* wsrc = Wp + (size_t)kbase * 512 + ci * 128;
                    for (int i = tid; i < (pkk << 7); i += 256) {
                        int kk = i >> 7, n = i & 127;
                        ws[kk * PADW + n] = wsrc[(size_t)kk * 512 + n];
                    }
                    __syncthreads();

                    const float* ap = A_s + kbase * PADA + ty * 8;
                    const float* wq = ws + 8 * tx;

#define GEMM_BODY(kk)                                                           \
    {                                                                           \
        float a_[8];                                                            \
        _Pragma("unroll")                                                       \
        for (int i = 0; i < 8; i++) a_[i] = ap[(kk) * PADA + i];                \
        float4 w0 = *(const float4*)(wq + (kk) * PADW);                         \
        float4 w1 = *(const float4*)(wq + (kk) * PADW + 4);                     \
        ull wq0 = pk2(w0.x, w0.y), wq1 = pk2(w0.z, w0.w);                       \
        ull wq2 = pk2(w1.x, w1.y), wq3 = pk2(w1.z, w1.w);                       \
        _Pragma("unroll")                                                       \
        for (int i = 0; i < 8; i++) {                                           \
            ull ad = pk2(a_[i], a_[i]);                                         \
            ffma2(acc[i][0], ad, wq0);                                          \
            ffma2(acc[i][1], ad, wq1);                                          \
            ffma2(acc[i][2], ad, wq2);                                          \
            ffma2(acc[i][3], ad, wq3);                                          \
        }                                                                       \
    }

                    if (pkk == 32) {
#pragma unroll 4
                        for (int kk = 0; kk < 32; ++kk) GEMM_BODY(kk)
                    } else {
                        for (int kk = 0; kk < pkk; ++kk) GEMM_BODY(kk)
                    }
#undef GEMM_BODY
                }

                // ---- cell epilogue: thread owns rows ty*8..+7, hiddens ci*32+2tx, +1 ----
                const int jg = ci * 32 + 2 * tx;
#pragma unroll
                for (int i = 0; i < 8; i++) {
                    const int row = ty * 8 + i;
                    float zi0, zf0, zg0, zo0, zi1, zf1, zg1, zo1;
                    upk2(acc[i][0], zi0, zf0);
                    upk2(acc[i][1], zg0, zo0);
                    upk2(acc[i][2], zi1, zf1);
                    upk2(acc[i][3], zg1, zo1);
                    float2 cc = *(float2*)&c_s[row * PADC + jg];
                    float c0n = sigf(zf0) * cc.x + sigf(zi0) * tanhf_(zg0);
                    float c1n = sigf(zf1) * cc.y + sigf(zi1) * tanhf_(zg1);
                    float h0 = sigf(zo0) * tanhf_(c0n);
                    float h1 = sigf(zo1) * tanhf_(c1n);
                    *(float2*)&c_s[row * PADC + jg] = make_float2(c0n, c1n);
                    *(float2*)&hdst[(size_t)(b0 + row) * 128 + jg] = make_float2(h0, h1);
                }
            }
        }
    }
}

// ---------------- final projection: out = r2 @ Wcomb^T + bcomb ----------------
__global__ void out_kernel(const float* __restrict__ r2, float* __restrict__ out)
{
    __shared__ float sw[NYv * 129];
    __shared__ float sr[32][129];
    int tid = threadIdx.x;
    for (int i = tid; i < NYv * Hv; i += 128) {
        int y = i >> 7, k = i & 127;
        sw[y * 129 + k] = g_wcomb[i];
    }
    size_t base = (size_t)blockIdx.x * 32 * Hv;
    for (int i = tid; i < 32 * Hv; i += 128) {
        int rr = i >> 7, kk = i & 127;
        sr[rr][kk] = r2[base + i];
    }
    __syncthreads();
    int r = tid >> 2, y = tid & 3;
    int n = blockIdx.x * 32 + r;
    int t = n >> 14;
    int b = n & (Bv - 1);
    float acc = g_bcomb[y];
#pragma unroll 4
    for (int k = 0; k < Hv; k++) acc += sw[y * 129 + k] * sr[r][k];
    out[((size_t)b * Tv + t) * NYv + y] = acc;
}

// ---------------- out_sfc = hN @ Wsfc^T + bsfc ----------------
__global__ void sfc_kernel(const float* __restrict__ Wsfc, const float* __restrict__ bsfc,
                           const float* __restrict__ hN, float* __restrict__ osfc)
{
    int i = blockIdx.x * blockDim.x + threadIdx.x;
    if (i >= Bv * NYSv) return;
    int b = i / 3, y = i - b * 3;
    const float* h = hN + (size_t)b * Hv;
    float acc = bsfc[y];
#pragma unroll 4
    for (int k = 0; k < Hv; k++) acc += Wsfc[y * Hv + k] * h[k];
    osfc[i] = acc;
}

// ---------------- launch ----------------
extern "C" void kernel_launch(void* const* d_in, const int* in_sizes, int n_in,
                              void* d_out, int out_size)
{
    const float* inputs_main = (const float*)d_in[0];
    const float* inputs_sfc  = (const float*)d_in[1];
    const float* mem0        = (const float*)d_in[2];
    const float* hx2         = (const float*)d_in[3];
    const float* cx2         = (const float*)d_in[4];
    const float* Ws1  = (const float*)d_in[5];
    const float* bs1  = (const float*)d_in[6];
    const float* Ws2  = (const float*)d_in[7];
    const float* bs2  = (const float*)d_in[8];
    const float* Wih1 = (const float*)d_in[9];
    const float* Whh1 = (const float*)d_in[10];
    const float* bih1 = (const float*)d_in[11];
    const float* bhh1 = (const float*)d_in[12];
    const float* Wih2 = (const float*)d_in[13];
    const float* Whh2 = (const float*)d_in[14];
    const float* bih2 = (const float*)d_in[15];
    const float* bhh2 = (const float*)d_in[16];
    const float* Wlat = (const float*)d_in[17];
    const float* blat = (const float*)d_in[18];
    const float* Wout = (const float*)d_in[19];
    const float* bout = (const float*)d_in[20];
    const float* Wsfc = (const float*)d_in[21];
    const float* bsfc = (const float*)d_in[22];
    float* out = (float*)d_out;

    float *r1, *r2, *h1, *c1, *W1p, *W2p, *b1p, *b2p;
    cudaGetSymbolAddress((void**)&r1, g_r1);
    cudaGetSymbolAddress((void**)&r2, g_r2);
    cudaGetSymbolAddress((void**)&h1, g_h1);
    cudaGetSymbolAddress((void**)&c1, g_c1);
    cudaGetSymbolAddress((void**)&W1p, g_W1p);
    cudaGetSymbolAddress((void**)&W2p, g_W2p);
    cudaGetSymbolAddress((void**)&b1p, g_b1p);
    cudaGetSymbolAddress((void**)&b2p, g_b2p);

    const int SMEM_BYTES = (260 * PADA + 128 * PADC + 32 * PADW + 512) * 4;
    cudaFuncSetAttribute(rnn_persist, cudaFuncAttributeMaxDynamicSharedMemorySize, SMEM_BYTES);

    init_kernel<<<(Bv * Hv + 255) / 256, 256>>>(inputs_sfc, Ws1, bs1, Ws2, bs2);

    const int PREP_N = 260 * 512 + 256 * 512 + 512;
    prep_kernel<<<(PREP_N + 255) / 256, 256>>>(Wih1, Whh1, bih1, bhh1,
                                               Wih2, Whh2, bih2, bhh2,
                                               Wlat, blat, Wout, bout);

    rnn_persist<<<128, 256, SMEM_BYTES>>>(inputs_main, mem0, h1, c1, hx2, cx2,
                                          W1p, b1p, W2p, b2p, r1, r2);

    out_kernel<<<(Bv * Tv) / 32, 128>>>(r2, out);
    sfc_kernel<<<(Bv * NYSv + 255) / 256, 256>>>(Wsfc, bsfc,
                                                 r2 + (size_t)(Tv - 1) * Bv * Hv,
                                                 out + (size_t)Bv * Tv * NYv);
}

// round 15
// speedup vs baseline: 3.5581x; 3.5581x over previous
#include <cuda_runtime.h>
#include <cuda_bf16.h>
#include <math.h>

#define Bv   16384
#define Tv   60
#define Hv   128
#define NXv  4
#define NYv  4
#define NYSv 3

typedef unsigned int u32;

// ---- SMEM layout (bytes): A_hi[0,64K) A_lo[64K,128K) B ring[128K,192K) bias wx xs
#define B_OFF    131072
#define BIAS_OFF 196608
#define WX_OFF   198656
#define XS_OFF   206848
#define SMEM_SZ  208896

// ---- device scratch ----
__device__ char  g_Wslab[(size_t)2 * 16 * 32768];      // pre-swizzled bf16 weight slabs
__device__ float g_bp[2 * 512];
__device__ float g_Wx[512 * 4];
__device__ float g_h1[Bv * Hv];
__device__ float g_c1[Bv * Hv];
__device__ char  g_blob[(size_t)128 * Tv * 65536];     // layer1 h (hi 32KB + lo 32KB) per (cta,t)
__device__ char  g_hb2[(size_t)128 * 2 * 65536];       // layer2 h ping-pong
__device__ float g_r2[(size_t)Tv * Bv * Hv];
__device__ float g_wcomb[NYv * Hv];
__device__ float g_bcomb[NYv];

// ---- helpers ----
__device__ __forceinline__ u32 smem_u32(const void* p) {
    u32 a; asm("{ .reg .u64 t; cvta.to.shared.u64 t, %1; cvt.u32.u64 %0, t; }" : "=r"(a) : "l"(p));
    return a;
}
__device__ __forceinline__ void ldsm4(u32* r, u32 a) {
    asm volatile("ldmatrix.sync.aligned.m8n8.x4.shared.b16 {%0,%1,%2,%3}, [%4];"
        : "=r"(r[0]), "=r"(r[1]), "=r"(r[2]), "=r"(r[3]) : "r"(a));
}
__device__ __forceinline__ void mma_bf(float* d, const u32* a, const u32* b) {
    asm volatile("mma.sync.aligned.m16n8k16.row.col.f32.bf16.bf16.f32 "
        "{%0,%1,%2,%3},{%4,%5,%6,%7},{%8,%9},{%0,%1,%2,%3};"
        : "+f"(d[0]), "+f"(d[1]), "+f"(d[2]), "+f"(d[3])
        : "r"(a[0]), "r"(a[1]), "r"(a[2]), "r"(a[3]), "r"(b[0]), "r"(b[1]));
}
__device__ __forceinline__ void cpa16(u32 dst, const void* src) {
    asm volatile("cp.async.cg.shared.global [%0], [%1], 16;" :: "r"(dst), "l"(src));
}
#define CP_COMMIT() asm volatile("cp.async.commit_group;" ::: "memory")

__device__ __forceinline__ float sigf(float x)   { return __fdividef(1.0f, 1.0f + __expf(-x)); }
__device__ __forceinline__ float tanhf_(float x) { return __fdividef(2.0f, 1.0f + __expf(-2.0f * x)) - 1.0f; }
__device__ __forceinline__ u32 packbf(float a, float b) {
    __nv_bfloat162 t = __floats2bfloat162_rn(a, b);
    return *(u32*)&t;
}

// ---- init: layer1 h0/c0 ----
__global__ void init_kernel(const float* __restrict__ sfc,
                            const float* __restrict__ Ws1, const float* __restrict__ bs1,
                            const float* __restrict__ Ws2, const float* __restrict__ bs2)
{
    int i = blockIdx.x * blockDim.x + threadIdx.x;
    if (i >= Bv * Hv) return;
    int b = i >> 7, j = i & 127;
    float s0 = sfc[b*3+0], s1 = sfc[b*3+1], s2 = sfc[b*3+2];
    g_h1[i] = tanhf(bs1[j] + s0*Ws1[j*3+0] + s1*Ws1[j*3+1] + s2*Ws1[j*3+2]);
    g_c1[i] = tanhf(bs2[j] + s0*Ws2[j*3+0] + s1*Ws2[j*3+1] + s2*Ws2[j*3+2]);
}

// ---- prep: split+swizzle weight slabs, biases, Wx, folded out projection ----
// col permutation (per 128-wide ci chunk): q=(n>>3)&3, jj=((n>>5)<<3)+(n&7), g=q*128+ci*32+jj
__global__ void prep_kernel(const float* __restrict__ Wih1, const float* __restrict__ Whh1,
                            const float* __restrict__ bih1, const float* __restrict__ bhh1,
                            const float* __restrict__ Wih2, const float* __restrict__ Whh2,
                            const float* __restrict__ bih2, const float* __restrict__ bhh2,
                            const float* __restrict__ Wlat, const float* __restrict__ blat,
                            const float* __restrict__ Wout, const float* __restrict__ bout)
{
    int idx = blockIdx.x * blockDim.x + threadIdx.x;
    const int NB = 2 * 16 * 128 * 128;   // 524288
    if (idx < NB) {
        int layer = idx >> 18;
        int rem = idx & 262143;
        int slab = rem >> 14;            // ci*4 + sl
        int n = (rem >> 7) & 127, kloc = rem & 127;
        int ci = slab >> 2, sl = slab & 3, term = sl >> 1, kh = sl & 1;
        int k = kh * 128 + kloc;
        int q = (n >> 3) & 3, jj = ((n >> 5) << 3) + (n & 7);
        int g = q * 128 + ci * 32 + jj;
        float w;
        if (layer == 0) w = (k < 128) ? Wih1[g*132 + 4 + k] : Whh1[g*128 + k - 128];
        else            w = (k < 128) ? Wih2[g*128 + k]     : Whh2[g*128 + k - 128];
        __nv_bfloat16 hi = __float2bfloat16_rn(w);
        float lo = w - __bfloat162float(hi);
        __nv_bfloat16 v = term ? __float2bfloat16_rn(lo) : hi;
        size_t base = (size_t)(layer * 16 + slab) << 15;
        *(__nv_bfloat16*)(g_Wslab + base + n*256 + ((2*kloc) ^ ((n & 7) << 4))) = v;
        return;
    }
    int i2 = idx - NB;
    if (i2 < 2048) {   // Wx
        int m = i2 >> 2, f = i2 & 3;
        int ci = m >> 7, n = m & 127;
        int q = (n >> 3) & 3, jj = ((n >> 5) << 3) + (n & 7);
        int g = q * 128 + ci * 32 + jj;
        g_Wx[i2] = Wih1[g * 132 + f];
        return;
    }
    int i3 = i2 - 2048;
    if (i3 < 1024) {   // biases
        int layer = i3 >> 9, m = i3 & 511;
        int ci = m >> 7, n = m & 127;
        int q = (n >> 3) & 3, jj = ((n >> 5) << 3) + (n & 7);
        int g = q * 128 + ci * 32 + jj;
        g_bp[i3] = layer ? (bih2[g] + bhh2[g]) : (bih1[g] + bhh1[g]);
        return;
    }
    int i4 = i3 - 1024;
    if (i4 < 512) {
        int y = i4 >> 7, j = i4 & 127;
        float acc = 0.0f;
        for (int k = 0; k < Hv; k++) acc += Wout[y*Hv+k] * Wlat[k*Hv+j];
        g_wcomb[i4] = acc;
        if (i4 < NYv) {
            float bb = bout[i4];
            for (int k = 0; k < Hv; k++) bb += Wout[i4*Hv+k] * blat[k];
            g_bcomb[i4] = bb;
        }
    }
}

// ---- stage fp32 -> swizzled bf16 hi/lo into A (koff elements: 0 or 128) ----
__device__ __forceinline__ void conv_split(char* sm, const float* src, int srcStride, int koff, int tid)
{
    for (int idx = tid; idx < 8192; idx += 256) {
        int r = idx >> 6, kp = idx & 63;
        float2 v = *(const float2*)(src + (size_t)r * srcStride + kp * 2);
        __nv_bfloat16 h0 = __float2bfloat16_rn(v.x), h1 = __float2bfloat16_rn(v.y);
        u32 hw = (u32)*(unsigned short*)&h0 | ((u32)*(unsigned short*)&h1 << 16);
        u32 lw = packbf(v.x - __bfloat162float(h0), v.y - __bfloat162float(h1));
        int byte = r * 512 + (((koff + kp * 2) * 2) ^ ((r & 7) << 4));
        *(u32*)(sm + byte) = hw;
        *(u32*)(sm + 65536 + byte) = lw;
    }
}
// ---- copy pre-swizzled blob (hi 32KB + lo 32KB, 256B rows) into A at dstAdd (0 or 256) ----
__device__ __forceinline__ void copy_blob(char* sm, const char* src, int dstAdd, int tid)
{
    for (int i = tid; i < 2048; i += 256) {
        int r = i >> 4, cb = (i & 15) << 4;
        *(uint4*)(sm + r*512 + dstAdd + cb) = *(const uint4*)(src + r*256 + cb);
        *(uint4*)(sm + 65536 + r*512 + dstAdd + cb) = *(const uint4*)(src + 32768 + r*256 + cb);
    }
}
__device__ __forceinline__ void cp_slab(u32 dst, const char* src, int tid)
{
#pragma unroll
    for (int i = 0; i < 8; i++) cpa16(dst + tid*16 + i*4096, src + tid*16 + i*4096);
}

// ---- persistent HMMA 2-layer LSTM ----
__global__ __launch_bounds__(256, 1) void rnn_mma(
    const float* __restrict__ inputs_main,   // [B][T][4]
    const float* __restrict__ mem0,          // [B][T][128]
    const float* __restrict__ hx2, const float* __restrict__ cx2)
{
    extern __shared__ char sm[];
    float* bias_s = (float*)(sm + BIAS_OFF);
    float* wx_s   = (float*)(sm + WX_OFF);
    float* xs_s   = (float*)(sm + XS_OFF);
    const u32 sb = smem_u32(sm);
    const int tid = threadIdx.x;
    const int w = tid >> 5, l = tid & 31;
    const int wm = w >> 2, wn = w & 3;
    const int lr = l >> 2, cc0 = 2 * (l & 3);
    const int bB = blockIdx.x * 128;
    const size_t SLAB = (size_t)Bv * Hv;

    // ldmatrix per-thread address pieces
    const int rA = wm * 64 + (l & 15);
    const u32 aBase = sb + rA * 512;
    const u32 kLaneA = (u32)((l >> 4) << 4);
    const u32 sxA = (u32)((rA & 7) << 4);
    const int nB = wn * 32 + ((l >> 4) << 3) + (l & 7);
    const u32 kLaneB = (u32)(((l >> 3) & 1) << 4);
    const u32 sxB = (u32)((l & 7) << 4);

    for (int i = tid; i < 2048; i += 256) wx_s[i] = g_Wx[i];

    float c_reg[64];
    float acc[4][4][4];

    for (int layer = 0; layer < 2; ++layer) {
        __syncthreads();
        for (int i = tid; i < 512; i += 256) bias_s[i] = g_bp[layer * 512 + i];
        {
            const float* c0 = layer ? cx2 : g_c1;
#pragma unroll
            for (int mi = 0; mi < 4; mi++)
#pragma unroll
            for (int rr = 0; rr < 2; rr++) {
                int row = wm*64 + mi*16 + lr + rr*8;
#pragma unroll
                for (int c4 = 0; c4 < 4; c4++) {
                    float2 v = *(const float2*)&c0[(size_t)(bB + row) * 128 + c4*32 + wn*8 + cc0];
                    c_reg[(mi*2+rr)*8 + c4*2]     = v.x;
                    c_reg[(mi*2+rr)*8 + c4*2 + 1] = v.y;
                }
            }
        }
        const char* wbase = g_Wslab + ((size_t)layer << 19);   // 16*32768

        for (int t = 0; t < Tv; ++t) {
            const int ta = layer ? t : (Tv - 1 - t);
            __syncthreads();   // everything from prev step done

            cp_slab(sb + B_OFF, wbase, tid); CP_COMMIT();
            cp_slab(sb + B_OFF + 32768, wbase + 32768, tid); CP_COMMIT();

            // ---- stage A ----
            if (layer == 0) {
                conv_split(sm, mem0 + ((size_t)bB * Tv + t) * 128, Tv * 128, 0, tid);
                if (t == 0) conv_split(sm, g_h1 + (size_t)bB * 128, 128, 128, tid);
                else copy_blob(sm, g_blob + ((size_t)blockIdx.x * Tv + (ta + 1)) * 65536, 256, tid);
                if (tid < 128)
                    *(float4*)&xs_s[tid*4] = *(const float4*)(inputs_main + ((size_t)(bB + tid) * Tv + ta) * 4);
            } else {
                copy_blob(sm, g_blob + ((size_t)blockIdx.x * Tv + t) * 65536, 0, tid);
                if (t == 0) conv_split(sm, hx2 + (size_t)bB * 128, 128, 128, tid);
                else copy_blob(sm, g_hb2 + ((size_t)(blockIdx.x * 2 + ((t - 1) & 1))) * 65536, 256, tid);
            }
            __syncthreads();

            for (int s = 0; s < 16; ++s) {
                if (s < 15) asm volatile("cp.async.wait_group 1;" ::: "memory");
                else        asm volatile("cp.async.wait_group 0;" ::: "memory");
                __syncthreads();

                if ((s & 3) == 0) {   // init acc from bias for new ci
                    int bb0 = (s >> 2) * 128 + wn * 32 + cc0;
#pragma unroll
                    for (int ni = 0; ni < 4; ni++) {
                        float v0 = bias_s[bb0 + ni*8], v1 = bias_s[bb0 + ni*8 + 1];
#pragma unroll
                        for (int mi = 0; mi < 4; mi++) {
                            acc[mi][ni][0] = v0; acc[mi][ni][1] = v1;
                            acc[mi][ni][2] = v0; acc[mi][ni][3] = v1;
                        }
                    }
                }

                const u32 bbase = sb + B_OFF + ((u32)(s & 1) << 15) + nB * 256;
                const u32 kb0 = (u32)(s & 1) << 8;
                const bool hi_term = ((s >> 1) & 1) == 0;
#pragma unroll
                for (int kk = 0; kk < 8; kk++) {
                    u32 aoff = (((kb0 + kk*32) | kLaneA) ^ sxA);
                    u32 boff = ((((u32)kk << 5) | kLaneB) ^ sxB);
                    u32 b[8];
                    ldsm4(b, bbase + boff);
                    ldsm4(b + 4, bbase + 4096 + boff);
                    u32 a[16];
                    ldsm4(a,      aBase + aoff);
                    ldsm4(a + 4,  aBase + 8192 + aoff);
                    ldsm4(a + 8,  aBase + 16384 + aoff);
                    ldsm4(a + 12, aBase + 24576 + aoff);
#pragma unroll
                    for (int mi = 0; mi < 4; mi++)
#pragma unroll
                    for (int ni = 0; ni < 4; ni++)
                        mma_bf(acc[mi][ni], a + 4*mi, b + 2*ni);
                    if (hi_term) {
                        u32 al[16];
                        ldsm4(al,      aBase + 65536 + aoff);
                        ldsm4(al + 4,  aBase + 73728 + aoff);
                        ldsm4(al + 8,  aBase + 81920 + aoff);
                        ldsm4(al + 12, aBase + 90112 + aoff);
#pragma unroll
                        for (int mi = 0; mi < 4; mi++)
#pragma unroll
                        for (int ni = 0; ni < 4; ni++)
                            mma_bf(acc[mi][ni], al + 4*mi, b + 2*ni);
                    }
                }

                if ((s & 3) == 3) {   // ---- epilogue for ci ----
                    int ci = s >> 2;
                    int j0c = ci*32 + wn*8 + cc0;
                    float4 wq[4][2];
                    if (layer == 0) {
#pragma unroll
                        for (int q = 0; q < 4; q++) {
                            int ng = ci*128 + wn*32 + q*8 + cc0;
                            wq[q][0] = *(const float4*)&wx_s[ng * 4];
                            wq[q][1] = *(const float4*)&wx_s[ng * 4 + 4];
                        }
                    }
#pragma unroll
                    for (int mi = 0; mi < 4; mi++)
#pragma unroll
                    for (int rr = 0; rr < 2; rr++) {
                        int row = wm*64 + mi*16 + lr + rr*8;
                        float4 xr = make_float4(0.f, 0.f, 0.f, 0.f);
                        if (layer == 0) xr = *(const float4*)&xs_s[row * 4];
                        float hh[2];
#pragma unroll
                        for (int u = 0; u < 2; u++) {
                            float zi = acc[mi][0][rr*2+u], zf = acc[mi][1][rr*2+u];
                            float zg = acc[mi][2][rr*2+u], zo = acc[mi][3][rr*2+u];
                            if (layer == 0) {
                                zi += wq[0][u].x*xr.x + wq[0][u].y*xr.y + wq[0][u].z*xr.z + wq[0][u].w*xr.w;
                                zf += wq[1][u].x*xr.x + wq[1][u].y*xr.y + wq[1][u].z*xr.z + wq[1][u].w*xr.w;
                                zg += wq[2][u].x*xr.x + wq[2][u].y*xr.y + wq[2][u].z*xr.z + wq[2][u].w*xr.w;
                                zo += wq[3][u].x*xr.x + wq[3][u].y*xr.y + wq[3][u].z*xr.z + wq[3][u].w*xr.w;
                            }
                            int cidx = (mi*2+rr)*8 + ci*2 + u;
                            float cn = sigf(zf) * c_reg[cidx] + sigf(zi) * tanhf_(zg);
                            hh[u] = sigf(zo) * tanhf_(cn);
                            c_reg[cidx] = cn;
                        }
                        __nv_bfloat16 q0 = __float2bfloat16_rn(hh[0]), q1 = __float2bfloat16_rn(hh[1]);
                        u32 hw = (u32)*(unsigned short*)&q0 | ((u32)*(unsigned short*)&q1 << 16);
                        u32 lw = packbf(hh[0] - __bfloat162float(q0), hh[1] - __bfloat162float(q1));
                        int bo = row * 256 + ((2 * j0c) ^ ((row & 7) << 4));
                        if (layer == 0) {
                            char* bb = g_blob + ((size_t)blockIdx.x * Tv + ta) * 65536;
                            *(u32*)(bb + bo) = hw;
                            *(u32*)(bb + 32768 + bo) = lw;
                        } else {
                            char* bb = g_hb2 + ((size_t)(blockIdx.x * 2 + (t & 1))) * 65536;
                            *(u32*)(bb + bo) = hw;
                            *(u32*)(bb + 32768 + bo) = lw;
                            *(float2*)(g_r2 + (size_t)t * SLAB + (size_t)(bB + row) * 128 + j0c) =
                                make_float2(hh[0], hh[1]);
                        }
                    }
                }
                __syncthreads();
                if (s + 2 < 16) {
                    cp_slab(sb + B_OFF + ((u32)(s & 1) << 15), wbase + ((size_t)(s + 2) << 15), tid);
                    CP_COMMIT();
                }
            }
        }
    }
}

// ---- out = r2 @ Wcomb^T + bcomb ----
__global__ void out_kernel(const float* __restrict__ r2, float* __restrict__ out)
{
    __shared__ float sw[NYv * 129];
    __shared__ float sr[32][129];
    int tid = threadIdx.x;
    for (int i = tid; i < NYv * Hv; i += 128) {
        int y = i >> 7, k = i & 127;
        sw[y * 129 + k] = g_wcomb[i];
    }
    size_t base = (size_t)blockIdx.x * 32 * Hv;
    for (int i = tid; i < 32 * Hv; i += 128) {
        int rr = i >> 7, kk = i & 127;
        sr[rr][kk] = r2[base + i];
    }
    __syncthreads();
    int r = tid >> 2, y = tid & 3;
    int n = blockIdx.x * 32 + r;
    int t = n >> 14;
    int b = n & (Bv - 1);
    float acc = g_bcomb[y];
#pragma unroll 4
    for (int k = 0; k < Hv; k++) acc += sw[y * 129 + k] * sr[r][k];
    out[((size_t)b * Tv + t) * NYv + y] = acc;
}

__global__ void sfc_kernel(const float* __restrict__ Wsfc, const float* __restrict__ bsfc,
                           const float* __restrict__ hN, float* __restrict__ osfc)
{
    int i = blockIdx.x * blockDim.x + threadIdx.x;
    if (i >= Bv * NYSv) return;
    int b = i / 3, y = i - b * 3;
    const float* h = hN + (size_t)b * Hv;
    float acc = bsfc[y];
#pragma unroll 4
    for (int k = 0; k < Hv; k++) acc += Wsfc[y * Hv + k] * h[k];
    osfc[i] = acc;
}

// ---- launch ----
extern "C" void kernel_launch(void* const* d_in, const int* in_sizes, int n_in,
                              void* d_out, int out_size)
{
    const float* inputs_main = (const float*)d_in[0];
    const float* inputs_sfc  = (const float*)d_in[1];
    const float* mem0        = (const float*)d_in[2];
    const float* hx2         = (const float*)d_in[3];
    const float* cx2         = (const float*)d_in[4];
    const float* Ws1  = (const float*)d_in[5];
    const float* bs1  = (const float*)d_in[6];
    const float* Ws2  = (const float*)d_in[7];
    const float* bs2  = (const float*)d_in[8];
    const float* Wih1 = (const float*)d_in[9];
    const float* Whh1 = (const float*)d_in[10];
    const float* bih1 = (const float*)d_in[11];
    const float* bhh1 = (const float*)d_in[12];
    const float* Wih2 = (const float*)d_in[13];
    const float* Whh2 = (const float*)d_in[14];
    const float* bih2 = (const float*)d_in[15];
    const float* bhh2 = (const float*)d_in[16];
    const float* Wlat = (const float*)d_in[17];
    const float* blat = (const float*)d_in[18];
    const float* Wout = (const float*)d_in[19];
    const float* bout = (const float*)d_in[20];
    const float* Wsfc = (const float*)d_in[21];
    const float* bsfc = (const float*)d_in[22];
    float* out = (float*)d_out;

    float* r2;
    cudaGetSymbolAddress((void**)&r2, g_r2);

    init_kernel<<<(Bv * Hv + 255) / 256, 256>>>(inputs_sfc, Ws1, bs1, Ws2, bs2);

    const int PREP_N = 2*16*128*128 + 2048 + 1024 + 512;
    prep_kernel<<<(PREP_N + 255) / 256, 256>>>(Wih1, Whh1, bih1, bhh1,
                                               Wih2, Whh2, bih2, bhh2,
                                               Wlat, blat, Wout, bout);

    cudaFuncSetAttribute(rnn_mma, cudaFuncAttributeMaxDynamicSharedMemorySize, SMEM_SZ);
    rnn_mma<<<128, 256, SMEM_SZ>>>(inputs_main, mem0, hx2, cx2);

    out_kernel<<<(Bv * Tv) / 32, 128>>>(r2, out);
    sfc_kernel<<<(Bv * NYSv + 255) / 256, 256>>>(Wsfc, bsfc,
                                                 r2 + (size_t)(Tv - 1) * Bv * Hv,
                                                 out + (size_t)Bv * Tv * NYv);
}